// round 1
// baseline (speedup 1.0000x reference)
#include <cuda_runtime.h>
#include <mma.h>
#include <math.h>

using namespace nvcuda;

#define N_CELLS 16384
#define D_IN    512
#define D_HID   1024
#define D_OUT   512
#define MLP_W   128
#define G3H     3072
#define NF      8
#define FS      2048

// ---------------- device scratch (static, allocation-free) ----------------
__device__ float d_xvec[256];                       // [xa | xg] fused bias (ba1 + x@Wa1[:512])
__device__ float d_w2cat[256 * 512];                // [Wa2 ; -Wg2]
__device__ float d_bias2[512];                      // ba2 - bg2
__device__ float d_srelu[(size_t)N_CELLS * 256];    // relu hidden activations (a|g)
__device__ float d_soutput[(size_t)N_CELLS * 512];  // output = a - g
__device__ float d_tension[N_CELLS];
__device__ float d_ebuf[N_CELLS];
__device__ float d_gi[(size_t)N_CELLS * G3H];
__device__ float d_gh[(size_t)N_CELLS * G3H];
__device__ float d_hpost[(size_t)N_CELLS * D_HID];  // post GRU+mod+clip, pre-sync
__device__ float d_sumall[NF * D_HID];
__device__ float d_sumpos[NF * D_HID];
__device__ float d_sumneg[NF * D_HID];
__device__ float d_meanp[D_HID];
__device__ float d_meann[D_HID];
__device__ float d_F[NF * D_HID];
__device__ float d_gop[D_HID];
__device__ int   d_cntp[NF];
__device__ int   d_cntn[NF];
__device__ int   d_cnt_tot[2];
__device__ float d_tsum;
__device__ float d_sumexp;
__device__ int   d_tmax_i;
__device__ float d_cout[512];

__device__ __forceinline__ float to_tf32(float x) {
    float r;
    asm("cvt.rna.tf32.f32 %0, %1;" : "=f"(r) : "f"(x));
    return r;
}

// ---------------- generic tf32 WMMA GEMM: C = A[MxK] * B[KxN] + epilogue ----
// block tile 128x128, BK=32, 256 threads, warp grid 2x4 (warp tile 64x32)
// modes: 0 = +bias, 1 = relu(+bias), 2 = +bias + rowv[m]*colv[n]
__global__ void __launch_bounds__(256) gemm_tf32_kernel(
    const float* __restrict__ A, int lda,
    const float* __restrict__ B, int ldb,
    float* __restrict__ C, int ldc,
    int K, int mode,
    const float* __restrict__ bias,
    const float* __restrict__ rowv,
    const float* __restrict__ colv)
{
    __shared__ float smem[9472];
    float* As = smem;          // [128][40]  (cols 0..31 valid)
    float* Bs = smem + 5120;   // [32][136]  (cols 0..127 valid)
    float* Cs = smem;          // [128][72]  (reused after mainloop)

    const int tid  = threadIdx.x;
    const int bm   = blockIdx.y * 128;
    const int bn   = blockIdx.x * 128;
    const int warp = tid >> 5;
    const int wr   = warp & 1;   // 2 warp rows of 64
    const int wc   = warp >> 1;  // 4 warp cols of 32

    wmma::fragment<wmma::accumulator, 16, 16, 8, float> acc[4][2];
#pragma unroll
    for (int i = 0; i < 4; i++)
#pragma unroll
        for (int j = 0; j < 2; j++) wmma::fill_fragment(acc[i][j], 0.0f);

    const int arow = tid >> 3;
    const int acol = (tid & 7) << 2;
    const int bcol = (tid & 31) << 2;

    for (int k0 = 0; k0 < K; k0 += 32) {
        __syncthreads();
#pragma unroll
        for (int it = 0; it < 4; it++) {
            int r = arow + (it << 5);
            const float4 v = *reinterpret_cast<const float4*>(
                A + (size_t)(bm + r) * lda + k0 + acol);
            float* dst = As + r * 40 + acol;
            dst[0] = to_tf32(v.x); dst[1] = to_tf32(v.y);
            dst[2] = to_tf32(v.z); dst[3] = to_tf32(v.w);
        }
#pragma unroll
        for (int it = 0; it < 4; it++) {
            int r = (tid >> 5) + (it << 3);
            const float4 v = *reinterpret_cast<const float4*>(
                B + (size_t)(k0 + r) * ldb + bn + bcol);
            float* dst = Bs + r * 136 + bcol;
            dst[0] = to_tf32(v.x); dst[1] = to_tf32(v.y);
            dst[2] = to_tf32(v.z); dst[3] = to_tf32(v.w);
        }
        __syncthreads();
#pragma unroll
        for (int kk = 0; kk < 32; kk += 8) {
            wmma::fragment<wmma::matrix_a, 16, 16, 8, wmma::precision::tf32, wmma::row_major> af[4];
            wmma::fragment<wmma::matrix_b, 16, 16, 8, wmma::precision::tf32, wmma::row_major> bf[2];
#pragma unroll
            for (int i = 0; i < 4; i++)
                wmma::load_matrix_sync(af[i], As + (wr * 64 + i * 16) * 40 + kk, 40);
#pragma unroll
            for (int j = 0; j < 2; j++)
                wmma::load_matrix_sync(bf[j], Bs + kk * 136 + wc * 32 + j * 16, 136);
#pragma unroll
            for (int i = 0; i < 4; i++)
#pragma unroll
                for (int j = 0; j < 2; j++)
                    wmma::mma_sync(acc[i][j], af[i], bf[j], acc[i][j]);
        }
    }

    // epilogue in two 64-col halves staged through shared
#pragma unroll
    for (int h = 0; h < 2; h++) {
        __syncthreads();
        if ((wc >> 1) == h) {
            const int lc = (wc & 1) << 5;
#pragma unroll
            for (int i = 0; i < 4; i++)
#pragma unroll
                for (int j = 0; j < 2; j++)
                    wmma::store_matrix_sync(Cs + (wr * 64 + i * 16) * 72 + lc + j * 16,
                                            acc[i][j], 72, wmma::mem_row_major);
        }
        __syncthreads();
#pragma unroll
        for (int it = 0; it < 32; it++) {
            int idx = it * 256 + tid;
            int r = idx >> 6, c = idx & 63;
            int gr = bm + r, gc = bn + (h << 6) + c;
            float v = Cs[r * 72 + c] + bias[gc];
            if (mode == 1) v = fmaxf(v, 0.0f);
            else if (mode == 2) v += rowv[gr] * colv[gc];
            C[(size_t)gr * ldc + gc] = v;
        }
    }
}

// ---------------- small kernels ----------------
__global__ void init_kernel() {
    int t = threadIdx.x;
    d_cout[t] = 0.0f;
    if (t < NF) { d_cntp[t] = 0; d_cntn[t] = 0; }
    if (t == 0) { d_tsum = 0.0f; d_sumexp = 0.0f; d_tmax_i = 0; }
}

__global__ void count_kernel(const int* __restrict__ pos) {
    int i = blockIdx.x * 256 + threadIdx.x;
    int p = pos[i];
    int f = i >> 11;
    if (p > 0) atomicAdd(&d_cntp[f], 1);
    else if (p < 0) atomicAdd(&d_cntn[f], 1);
}

// xvec[n] = ba1[n] + sum_k x[k]*Wa1[k,n]  (n<128), same for Wg1 at n>=128
__global__ void prep_kernel(const float* __restrict__ x,
                            const float* __restrict__ Wa1, const float* __restrict__ ba1,
                            const float* __restrict__ Wg1, const float* __restrict__ bg1) {
    int n = threadIdx.x;                  // 0..255
    const float* W = (n < 128) ? Wa1 : Wg1;
    int col = n & 127;
    float s = (n < 128) ? ba1[col] : bg1[col];
    for (int k = 0; k < D_IN; k++) s += x[k] * W[k * 128 + col];
    d_xvec[n] = s;
}

__global__ void w2cat_kernel(const float* __restrict__ Wa2, const float* __restrict__ ba2,
                             const float* __restrict__ Wg2, const float* __restrict__ bg2) {
    int r = blockIdx.x, c = threadIdx.x;  // 256 x 512
    d_w2cat[r * 512 + c] = (r < 128) ? Wa2[r * 512 + c] : -Wg2[(r - 128) * 512 + c];
    if (r == 0) d_bias2[c] = ba2[c] - bg2[c];
}

// tension[i] = mean(output[i,:]^2); also global sum + max
__global__ void tension_kernel() {
    int row  = blockIdx.x * 8 + (threadIdx.x >> 5);
    int lane = threadIdx.x & 31;
    const float* o = d_soutput + (size_t)row * 512;
    float s = 0.0f;
    for (int c = lane; c < 512; c += 32) { float v = o[c]; s += v * v; }
#pragma unroll
    for (int off = 16; off; off >>= 1) s += __shfl_xor_sync(0xffffffffu, s, off);
    __shared__ float wsum[8];
    __shared__ float wmax[8];
    float t = s * (1.0f / 512.0f);
    if (lane == 0) {
        d_tension[row] = t;
        wsum[threadIdx.x >> 5] = t;
        wmax[threadIdx.x >> 5] = t;
    }
    __syncthreads();
    if (threadIdx.x == 0) {
        float a = 0.0f, m = 0.0f;
        for (int w = 0; w < 8; w++) { a += wsum[w]; m = fmaxf(m, wmax[w]); }
        atomicAdd(&d_tsum, a);
        atomicMax(&d_tmax_i, __float_as_int(m));   // tension >= 0 so int cmp is fine
    }
}

__global__ void sumexp_kernel() {
    int i = blockIdx.x * 256 + threadIdx.x;
    float tmax = __int_as_float(d_tmax_i);
    float e = expf(d_tension[i] - tmax);
    d_ebuf[i] = e;
    __shared__ float sh[256];
    sh[threadIdx.x] = e;
    __syncthreads();
    for (int s = 128; s; s >>= 1) {
        if (threadIdx.x < s) sh[threadIdx.x] += sh[threadIdx.x + s];
        __syncthreads();
    }
    if (threadIdx.x == 0) atomicAdd(&d_sumexp, sh[0]);
}

// GRU combine + wealth mod + clip
__global__ void gru_kernel(const float* __restrict__ hid, const float* __restrict__ wealth) {
    size_t idx = (size_t)blockIdx.x * 256 + threadIdx.x;
    int i = (int)(idx >> 10), j = (int)(idx & 1023);
    size_t b = (size_t)i * G3H + j;
    float gir = d_gi[b],            ghr = d_gh[b];
    float giz = d_gi[b + 1024],     ghz = d_gh[b + 1024];
    float gin = d_gi[b + 2048],     ghn = d_gh[b + 2048];
    float r = 1.0f / (1.0f + expf(-(gir + ghr)));
    float z = 1.0f / (1.0f + expf(-(giz + ghz)));
    float n = tanhf(gin + r * ghn);
    float h = hid[idx];
    float nh = (1.0f - z) * n + z * h;
    float w = wealth[i];
    float mod = 0.9f + 0.1f * fminf(fmaxf(w, 0.1f), 2.0f);
    nh = fminf(fmaxf(nh * mod, -10.0f), 10.0f);
    d_hpost[idx] = nh;
}

// per-faction column sums (all / pos>0 / pos<0)
__global__ void stats_kernel(const int* __restrict__ pos) {
    int f = blockIdx.x;            // faction
    int j = blockIdx.y * 128 + threadIdx.x;
    int base = f * FS;
    float sa = 0.0f, sp = 0.0f, sn = 0.0f;
    for (int r = 0; r < FS; r++) {
        float v = d_hpost[(size_t)(base + r) * D_HID + j];
        int p = pos[base + r];
        sa += v;
        if (p > 0) sp += v; else if (p < 0) sn += v;
    }
    d_sumall[f * D_HID + j] = sa;
    d_sumpos[f * D_HID + j] = sp;
    d_sumneg[f * D_HID + j] = sn;
}

__global__ void statsfinal_kernel() {
    int j = threadIdx.x;           // 0..1023
    int cp = 0, cn = 0;
    for (int f = 0; f < NF; f++) { cp += d_cntp[f]; cn += d_cntn[f]; }
    float sp = 0.0f, sn = 0.0f;
    for (int f = 0; f < NF; f++) { sp += d_sumpos[f * D_HID + j]; sn += d_sumneg[f * D_HID + j]; }
    float mp = sp / (float)max(cp, 1);
    float mn = sn / (float)max(cn, 1);
    d_meanp[j] = mp; d_meann[j] = mn;
    float g = 0.0f;
    for (int f = 0; f < NF; f++) {
        float adj = d_sumall[f * D_HID + j];
        if (cp >= 2) adj += 0.1f * ((float)d_cntp[f] * mp - d_sumpos[f * D_HID + j]);
        if (cn >= 2) adj += 0.1f * ((float)d_cntn[f] * mn - d_sumneg[f * D_HID + j]);
        float F = adj * (1.0f / (float)FS);
        d_F[f * D_HID + j] = F;
        g += F;
    }
    d_gop[j] = g * (1.0f / (float)NF);
    if (j == 0) { d_cnt_tot[0] = cp; d_cnt_tot[1] = cn; }
}

// apply group syncs + faction sync + debate, write new_h into d_out
__global__ void final_kernel(const int* __restrict__ pos, const int* __restrict__ step,
                             float* __restrict__ out) {
    size_t idx = (size_t)blockIdx.x * 256 + threadIdx.x;
    int i = (int)(idx >> 10), j = (int)(idx & 1023);
    float h = d_hpost[idx];
    int p = pos[i];
    int cp = d_cnt_tot[0], cn = d_cnt_tot[1];
    if (p > 0 && cp >= 2)      h = 0.9f * h + 0.1f * d_meanp[j];
    else if (p < 0 && cn >= 2) h = 0.9f * h + 0.1f * d_meann[j];
    int f = i >> 11;
    h = 0.85f * h + 0.15f * d_F[f * D_HID + j];
    if (*step > 5 && (i & (FS - 1)) < (FS / 4)) h = 0.85f * h + 0.15f * d_gop[j];
    out[513 + idx] = h;
}

// combined_out = sum_i softmax(tension)_i * output[i,:]
__global__ void wsum_kernel() {
    int r0 = blockIdx.x * 256;
    float inv = 1.0f / d_sumexp;
    int t = threadIdx.x;
    float c0 = 0.0f, c1 = 0.0f;
    for (int r = r0; r < r0 + 256; r++) {
        float w = d_ebuf[r] * inv;
        const float* o = d_soutput + (size_t)r * 512;
        c0 += w * o[t];
        c1 += w * o[t + 256];
    }
    atomicAdd(&d_cout[t], c0);
    atomicAdd(&d_cout[t + 256], c1);
}

__global__ void pred_kernel(const float* __restrict__ Wo, const float* __restrict__ bo,
                            float* __restrict__ out) {
    __shared__ float co[512];
    int t = threadIdx.x;
    co[t] = d_cout[t];
    __syncthreads();
    float s = bo[t];
    for (int k = 0; k < 512; k++) s += co[k] * Wo[k * 512 + t];
    out[t] = s;
    if (t == 0) out[512] = d_tsum * (1.0f / (float)N_CELLS);
}

// ---------------- launch ----------------
extern "C" void kernel_launch(void* const* d_in, const int* in_sizes, int n_in,
                              void* d_out, int out_size) {
    const float* x        = (const float*)d_in[0];
    const float* hiddens  = (const float*)d_in[1];
    const float* wealth   = (const float*)d_in[2];
    const float* Wa1      = (const float*)d_in[3];
    const float* ba1      = (const float*)d_in[4];
    const float* Wa2      = (const float*)d_in[5];
    const float* ba2      = (const float*)d_in[6];
    const float* Wg1      = (const float*)d_in[7];
    const float* bg1      = (const float*)d_in[8];
    const float* Wg2      = (const float*)d_in[9];
    const float* bg2      = (const float*)d_in[10];
    const float* W_ih     = (const float*)d_in[11];
    const float* W_hh     = (const float*)d_in[12];
    const float* b_ih     = (const float*)d_in[13];
    const float* b_hh     = (const float*)d_in[14];
    const float* Wo       = (const float*)d_in[15];
    const float* bo       = (const float*)d_in[16];
    const int*   positions= (const int*)d_in[17];
    const int*   step     = (const int*)d_in[18];
    float* out = (float*)d_out;

    void *p_srelu, *p_soutput, *p_gi, *p_gh, *p_w2cat, *p_bias2, *p_xvec, *p_tension;
    cudaGetSymbolAddress(&p_srelu,   d_srelu);
    cudaGetSymbolAddress(&p_soutput, d_soutput);
    cudaGetSymbolAddress(&p_gi,      d_gi);
    cudaGetSymbolAddress(&p_gh,      d_gh);
    cudaGetSymbolAddress(&p_w2cat,   d_w2cat);
    cudaGetSymbolAddress(&p_bias2,   d_bias2);
    cudaGetSymbolAddress(&p_xvec,    d_xvec);
    cudaGetSymbolAddress(&p_tension, d_tension);

    init_kernel<<<1, 512>>>();
    count_kernel<<<64, 256>>>(positions);
    prep_kernel<<<1, 256>>>(x, Wa1, ba1, Wg1, bg1);
    w2cat_kernel<<<256, 512>>>(Wa2, ba2, Wg2, bg2);

    // H1 = relu(hiddens @ W1[512:] + xvec)  (a-half then g-half)
    gemm_tf32_kernel<<<dim3(1, 128), 256>>>(
        hiddens, 1024, Wa1 + 512 * 128, 128, (float*)p_srelu, 256,
        1024, 1, (float*)p_xvec, nullptr, nullptr);
    gemm_tf32_kernel<<<dim3(1, 128), 256>>>(
        hiddens, 1024, Wg1 + 512 * 128, 128, (float*)p_srelu + 128, 256,
        1024, 1, (float*)p_xvec + 128, nullptr, nullptr);

    // output = H1 @ [Wa2 ; -Wg2] + (ba2-bg2)
    gemm_tf32_kernel<<<dim3(4, 128), 256>>>(
        (const float*)p_srelu, 256, (const float*)p_w2cat, 512,
        (float*)p_soutput, 512, 256, 0, (float*)p_bias2, nullptr, nullptr);

    tension_kernel<<<2048, 256>>>();
    sumexp_kernel<<<64, 256>>>();

    // gi = output @ W_ih[:512] + tension x W_ih[512] + b_ih
    gemm_tf32_kernel<<<dim3(24, 128), 256>>>(
        (const float*)p_soutput, 512, W_ih, 3072, (float*)p_gi, 3072,
        512, 2, b_ih, (const float*)p_tension, W_ih + (size_t)512 * 3072);
    // gh = hiddens @ W_hh + b_hh
    gemm_tf32_kernel<<<dim3(24, 128), 256>>>(
        hiddens, 1024, W_hh, 3072, (float*)p_gh, 3072,
        1024, 0, b_hh, nullptr, nullptr);

    gru_kernel<<<65536, 256>>>(hiddens, wealth);

    stats_kernel<<<dim3(8, 8), 128>>>(positions);
    statsfinal_kernel<<<1, 1024>>>();
    final_kernel<<<65536, 256>>>(positions, step, out);

    wsum_kernel<<<64, 256>>>();
    pred_kernel<<<1, 512>>>(Wo, bo, out);
}